// round 1
// baseline (speedup 1.0000x reference)
#include <cuda_runtime.h>

#define IMG_H 512
#define IMG_W 512
#define TILE_H 16
#define NTHREADS 256
#define VSTRIDE 520   // words per vsum row: 516 used (512 cols + 4 halo) + pad, 16B-aligned rows

__device__ __forceinline__ int reflr(int g) {
    // reflect-101: -1 -> 1, -2 -> 2, 512 -> 510, 513 -> 509
    g = g < 0 ? -g : g;
    if (g >= IMG_H) g = 2 * IMG_H - 2 - g;
    return g;
}

__global__ __launch_bounds__(NTHREADS)
void smooth5_kernel(const float* __restrict__ in, float* __restrict__ out)
{
    __shared__ __align__(16) float vs[TILE_H * VSTRIDE];

    const int tid   = threadIdx.x;
    const int plane = blockIdx.y;
    const int row0  = blockIdx.x * TILE_H;

    const float* ip = in  + (size_t)plane * (IMG_H * IMG_W);
    float*       op = out + (size_t)plane * (IMG_H * IMG_W);

    // ---- Phase 1: vertical 5-row sliding sums ----
    // Each thread owns columns tid and tid+256. vsum index cc = col + 2.
    // Horizontal halo (vsum idx 0,1,514,515) maps via reflect-101 to source
    // columns 2,1,510,509 — computed directly by threads 0..3.
    const int colA = tid;
    const int colB = tid + 256;

    int haloIdx = -1, haloCol = 0;
    if (tid < 4) {
        const int hidx[4] = {0, 1, 514, 515};
        const int hcol[4] = {2, 1, 510, 509};
        haloIdx = hidx[tid];
        haloCol = hcol[tid];
    }

    float a0, a1, a2, a3;   // colA window (last 4 rows)
    float b0, b1, b2, b3;   // colB window
    float h0 = 0.f, h1 = 0.f, h2 = 0.f, h3 = 0.f;

    {
        const float* r0p = ip + (size_t)reflr(row0 - 2) * IMG_W;
        const float* r1p = ip + (size_t)reflr(row0 - 1) * IMG_W;
        const float* r2p = ip + (size_t)(row0)          * IMG_W;
        const float* r3p = ip + (size_t)(row0 + 1)      * IMG_W;
        a0 = r0p[colA]; b0 = r0p[colB];
        a1 = r1p[colA]; b1 = r1p[colB];
        a2 = r2p[colA]; b2 = r2p[colB];
        a3 = r3p[colA]; b3 = r3p[colB];
        if (haloIdx >= 0) {
            h0 = r0p[haloCol]; h1 = r1p[haloCol];
            h2 = r2p[haloCol]; h3 = r3p[haloCol];
        }
    }

    #pragma unroll 4
    for (int r = 0; r < TILE_H; ++r) {
        const float* rp = ip + (size_t)reflr(row0 + 2 + r) * IMG_W;
        float na = rp[colA];
        float nb = rp[colB];
        vs[r * VSTRIDE + 2 + colA] = a0 + a1 + a2 + a3 + na;
        vs[r * VSTRIDE + 2 + colB] = b0 + b1 + b2 + b3 + nb;
        a0 = a1; a1 = a2; a2 = a3; a3 = na;
        b0 = b1; b1 = b2; b2 = b3; b3 = nb;
        if (haloIdx >= 0) {
            float nh = rp[haloCol];
            vs[r * VSTRIDE + haloIdx] = h0 + h1 + h2 + h3 + nh;
            h0 = h1; h1 = h2; h2 = h3; h3 = nh;
        }
    }

    __syncthreads();

    // ---- Phase 2: horizontal 5-tap from SMEM, 4 outputs per task ----
    // 16 rows x 128 float4-groups = 2048 tasks; 8 per thread.
    const float inv25 = 1.0f / 25.0f;
    #pragma unroll
    for (int j = 0; j < (TILE_H * (IMG_W / 4)) / NTHREADS; ++j) {
        int task = tid + j * NTHREADS;
        int r = task >> 7;       // / 128
        int q = task & 127;      // float4 group within row
        const float* vr = vs + r * VSTRIDE + 4 * q;
        float4 A  = *reinterpret_cast<const float4*>(vr);
        float4 Bv = *reinterpret_cast<const float4*>(vr + 4);
        float4 o;
        o.x = (A.x + A.y + A.z + A.w + Bv.x) * inv25;
        o.y = (A.y + A.z + A.w + Bv.x + Bv.y) * inv25;
        o.z = (A.z + A.w + Bv.x + Bv.y + Bv.z) * inv25;
        o.w = (A.w + Bv.x + Bv.y + Bv.z + Bv.w) * inv25;
        *reinterpret_cast<float4*>(op + (size_t)(row0 + r) * IMG_W + 4 * q) = o;
    }
}

extern "C" void kernel_launch(void* const* d_in, const int* in_sizes, int n_in,
                              void* d_out, int out_size)
{
    const float* in  = (const float*)d_in[0];
    float*       out = (float*)d_out;
    // planes = B*C derived from input size; w is fixed at 5 by the problem.
    int planes = in_sizes[0] / (IMG_H * IMG_W);
    dim3 grid(IMG_H / TILE_H, planes);
    smooth5_kernel<<<grid, NTHREADS>>>(in, out);
}

// round 2
// speedup vs baseline: 1.0998x; 1.0998x over previous
#include <cuda_runtime.h>

#define IMG_H 512
#define IMG_W 512
#define TILE_H 16
#define NTHREADS 256
#define VSTRIDE 520   // floats per vsum row: 516 used (2 halo + 512 + 2 halo) + pad

__device__ __forceinline__ int reflr(int g) {
    // reflect-101: -1 -> 1, -2 -> 2, 512 -> 510, 513 -> 509
    g = g < 0 ? -g : g;
    if (g >= IMG_H) g = 2 * IMG_H - 2 - g;
    return g;
}

__global__ __launch_bounds__(NTHREADS)
void smooth5_kernel(const float* __restrict__ in, float* __restrict__ out)
{
    __shared__ __align__(16) float vs[TILE_H * VSTRIDE];

    const int tid   = threadIdx.x;
    const int plane = blockIdx.y;
    const int row0  = blockIdx.x * TILE_H;

    const float* ip = in  + (size_t)plane * (IMG_H * IMG_W);
    float*       op = out + (size_t)plane * (IMG_H * IMG_W);

    // ---- Phase 1: vertical 5-row sliding sums, float2 per thread ----
    // Thread owns columns c0 = 2*tid, c0+1. vsum slot = col + 2.
    // Halo slots 0,1,514,515 hold vsums of cols 2,1,510,509 (reflect-101) —
    // those are values some thread already computed; it just stores one extra word.
    const int c0 = 2 * tid;

    int  haloSlot = -1;
    bool haloY    = false;
    if      (tid == 0)   { haloSlot = 1;   haloY = true;  }  // col 1
    else if (tid == 1)   { haloSlot = 0;   haloY = false; }  // col 2
    else if (tid == 254) { haloSlot = 515; haloY = true;  }  // col 509
    else if (tid == 255) { haloSlot = 514; haloY = false; }  // col 510

    const int rowStride2 = IMG_W / 2;   // float2 per row
    const float2* ipc = reinterpret_cast<const float2*>(ip) + tid;

    float2 w0, w1, w2, w3;

    if (row0 >= 2 && row0 + TILE_H + 2 <= IMG_H) {
        // -------- interior fast path: pure pointer increments --------
        const float2* rp = ipc + (size_t)(row0 - 2) * rowStride2;
        w0 = rp[0];             rp += rowStride2;
        w1 = rp[0];             rp += rowStride2;
        w2 = rp[0];             rp += rowStride2;
        w3 = rp[0];             rp += rowStride2;
        #pragma unroll
        for (int r = 0; r < TILE_H; ++r) {
            float2 n = rp[0];   rp += rowStride2;
            float2 v;
            v.x = w0.x + w1.x + w2.x + w3.x + n.x;
            v.y = w0.y + w1.y + w2.y + w3.y + n.y;
            *reinterpret_cast<float2*>(&vs[r * VSTRIDE + 2 + c0]) = v;
            if (haloSlot >= 0) vs[r * VSTRIDE + haloSlot] = haloY ? v.y : v.x;
            w0 = w1; w1 = w2; w2 = w3; w3 = n;
        }
    } else {
        // -------- boundary blocks: reflected row indexing --------
        w0 = ipc[(size_t)reflr(row0 - 2) * rowStride2];
        w1 = ipc[(size_t)reflr(row0 - 1) * rowStride2];
        w2 = ipc[(size_t)(row0)          * rowStride2];
        w3 = ipc[(size_t)(row0 + 1)      * rowStride2];
        #pragma unroll
        for (int r = 0; r < TILE_H; ++r) {
            float2 n = ipc[(size_t)reflr(row0 + 2 + r) * rowStride2];
            float2 v;
            v.x = w0.x + w1.x + w2.x + w3.x + n.x;
            v.y = w0.y + w1.y + w2.y + w3.y + n.y;
            *reinterpret_cast<float2*>(&vs[r * VSTRIDE + 2 + c0]) = v;
            if (haloSlot >= 0) vs[r * VSTRIDE + haloSlot] = haloY ? v.y : v.x;
            w0 = w1; w1 = w2; w2 = w3; w3 = n;
        }
    }

    __syncthreads();

    // ---- Phase 2: horizontal 5-tap from SMEM, 4 outputs per task ----
    const float inv25 = 1.0f / 25.0f;
    #pragma unroll
    for (int j = 0; j < (TILE_H * (IMG_W / 4)) / NTHREADS; ++j) {
        int task = tid + j * NTHREADS;
        int r = task >> 7;       // / 128
        int q = task & 127;      // float4 group within row
        const float* vr = vs + r * VSTRIDE + 4 * q;
        float4 A  = *reinterpret_cast<const float4*>(vr);
        float4 Bv = *reinterpret_cast<const float4*>(vr + 4);
        float4 o;
        o.x = (A.x + A.y + A.z + A.w + Bv.x) * inv25;
        o.y = (A.y + A.z + A.w + Bv.x + Bv.y) * inv25;
        o.z = (A.z + A.w + Bv.x + Bv.y + Bv.z) * inv25;
        o.w = (A.w + Bv.x + Bv.y + Bv.z + Bv.w) * inv25;
        *reinterpret_cast<float4*>(op + (size_t)(row0 + r) * IMG_W + 4 * q) = o;
    }
}

extern "C" void kernel_launch(void* const* d_in, const int* in_sizes, int n_in,
                              void* d_out, int out_size)
{
    const float* in  = (const float*)d_in[0];
    float*       out = (float*)d_out;
    int planes = in_sizes[0] / (IMG_H * IMG_W);   // B*C
    dim3 grid(IMG_H / TILE_H, planes);
    smooth5_kernel<<<grid, NTHREADS>>>(in, out);
}